// round 1
// baseline (speedup 1.0000x reference)
#include <cuda_runtime.h>
#include <cuda_bf16.h>
#include <math.h>

#define V_SIZE 50257
#define EMB    512
#define HID    1024
#define AFEAT  64
#define TLEN   64
#define NBLK   128     // persistent LSTM blocks (<= SM count, all resident)
#define UNITS  8       // hidden units per block (128*8 = 1024)
#define ROWS   32      // gate rows per block (4 gates * 8 units)

// ---------------- device scratch (no allocations allowed) ----------------
__device__ float g_h[2][HID];          // double-buffered recurrent h
__device__ float g_hs[TLEN * HID];     // decoder hidden states
__device__ float g_rowsum[TLEN];       // per-step sum(exp(relu(logit)))
__device__ unsigned int g_count = 0;   // grid barrier arrivals
__device__ unsigned int g_gen = 0;     // grid barrier generation (monotonic forever)

__device__ __forceinline__ float sigf(float x) { return 1.0f / (1.0f + expf(-x)); }

// =========================================================================
// K1: persistent LSTM. 128 blocks x 256 threads, one grid barrier per step.
//   phase A: xproj[s][row] = x_s @ Wih_row + biases  (all 128 steps, in SMEM)
//   phase B: per-step GEMV h@Whh^T from SMEM-cached fp32 weights
// =========================================================================
#define K1_SMEM_FLOATS (32*1024 + 128*32 + 32 + 8)
#define K1_SMEM (K1_SMEM_FLOATS * sizeof(float))

__global__ void __launch_bounds__(256, 1) lstm_kernel(
    const int*   __restrict__ seq,  const float* __restrict__ feats,
    const int*   __restrict__ dseq, const float* __restrict__ emb,
    const float* __restrict__ eWih, const float* __restrict__ eWhh,
    const float* __restrict__ ebih, const float* __restrict__ ebhh,
    const float* __restrict__ dWih, const float* __restrict__ dWhh,
    const float* __restrict__ dbih, const float* __restrict__ dbhh)
{
    extern __shared__ float sm[];
    float* w_s     = sm;                    // [32][1024] Whh slice (fp32)
    float* xp_s    = sm + 32 * 1024;        // [128][32] input projections
    float* gates_s = xp_s + 128 * 32;       // [32]
    float* c_s     = gates_s + 32;          // [8]

    const int tid  = threadIdx.x;
    const int blk  = blockIdx.x;
    const int wid  = tid >> 5;
    const int lane = tid & 31;
    const int j0   = blk * UNITS;

    // Read the barrier generation BEFORE any arrival: no bump can happen
    // until all blocks arrive at barrier 1, so this is race-free.
    unsigned gen0 = 0;
    if (tid == 0) gen0 = *((volatile unsigned*)&g_gen);

    if (blk == 0 && tid < TLEN) g_rowsum[tid] = 0.0f;   // reset for K2 each launch
    if (tid < UNITS) c_s[tid] = 0.0f;

    // ---- phase A: input projections (warp per dot) ----
    for (int d = wid; d < 2048; d += 8) {
        const int s = d >> 5;
        const int r = d & 31;
        const int G = r >> 3;
        const int u = r & 7;
        const int row = G * HID + j0 + u;
        {   // encoder step s
            const float* x = emb + (size_t)seq[s] * EMB;
            const float* w = eWih + (size_t)row * EMB;
            float acc = 0.0f;
            #pragma unroll 4
            for (int k = lane; k < EMB; k += 32) acc = fmaf(x[k], w[k], acc);
            #pragma unroll
            for (int o = 16; o > 0; o >>= 1) acc += __shfl_down_sync(0xffffffffu, acc, o);
            if (lane == 0) xp_s[s * 32 + r] = acc + ebih[row] + ebhh[row];
        }
        {   // decoder step s (input = concat(embed, feats))
            const float* x = emb + (size_t)dseq[s] * EMB;
            const float* w = dWih + (size_t)row * (EMB + AFEAT);
            float acc = 0.0f;
            #pragma unroll 4
            for (int k = lane; k < EMB + AFEAT; k += 32) {
                float xv = (k < EMB) ? x[k] : feats[k - EMB];
                acc = fmaf(xv, w[k], acc);
            }
            #pragma unroll
            for (int o = 16; o > 0; o >>= 1) acc += __shfl_down_sync(0xffffffffu, acc, o);
            if (lane == 0) xp_s[(64 + s) * 32 + r] = acc + dbih[row] + dbhh[row];
        }
    }

    // ---- load encoder Whh slice into SMEM (fp32) ----
    for (int r = 0; r < ROWS; r++) {
        const int G = r >> 3, u = r & 7;
        const float4* src = (const float4*)(eWhh + (size_t)(G * HID + j0 + u) * HID);
        ((float4*)(w_s + r * HID))[tid] = src[tid];
    }
    __syncthreads();

    // ---- phase B: 128 recurrent steps ----
    for (int s = 0; s < 128; s++) {
        if (s == 64) {
            // swap SMEM slice to decoder Whh (enc weights last used in step 63)
            for (int r = 0; r < ROWS; r++) {
                const int G = r >> 3, u = r & 7;
                const float4* src = (const float4*)(dWhh + (size_t)(G * HID + j0 + u) * HID);
                ((float4*)(w_s + r * HID))[tid] = src[tid];
            }
            __syncthreads();
        }
        if (s > 0) {
            const float* hb = g_h[s & 1];
            float4 hr[8];   // lane covers k = q*128 + lane*4 + {0..3}
            #pragma unroll
            for (int q = 0; q < 8; q++)
                hr[q] = __ldcg((const float4*)(hb + q * 128 + lane * 4));
            #pragma unroll
            for (int rr = 0; rr < 4; rr++) {
                const int r = wid * 4 + rr;   // warp handles 4 rows
                const float4* wrow = (const float4*)(w_s + r * HID);
                float acc = 0.0f;
                #pragma unroll
                for (int q = 0; q < 8; q++) {
                    float4 w4 = wrow[q * 32 + lane];
                    acc = fmaf(w4.x, hr[q].x, acc);
                    acc = fmaf(w4.y, hr[q].y, acc);
                    acc = fmaf(w4.z, hr[q].z, acc);
                    acc = fmaf(w4.w, hr[q].w, acc);
                }
                #pragma unroll
                for (int o = 16; o > 0; o >>= 1) acc += __shfl_down_sync(0xffffffffu, acc, o);
                if (lane == 0) gates_s[r] = acc;
            }
        } else {
            if (tid < ROWS) gates_s[tid] = 0.0f;   // h0 = 0, skip dot
        }
        __syncthreads();

        if (tid < UNITS) {
            const int u = tid;
            const float* xp = xp_s + s * 32;
            float gi = gates_s[u]      + xp[u];        // i
            float gf = gates_s[8 + u]  + xp[8 + u];    // f
            float gg = gates_s[16 + u] + xp[16 + u];   // g
            float go = gates_s[24 + u] + xp[24 + u];   // o
            float c  = sigf(gf) * c_s[u] + sigf(gi) * tanhf(gg);
            c_s[u] = c;
            float h = sigf(go) * tanhf(c);
            const int j = j0 + u;
            __stcg(&g_h[(s + 1) & 1][j], h);
            if (s >= 64) __stcg(&g_hs[(s - 64) * HID + j], h);
            __threadfence();
        }

        // ---- grid barrier (generation = gen0 + s + 1) ----
        __syncthreads();
        if (tid == 0) {
            __threadfence();
            unsigned old = atomicAdd(&g_count, 1u);
            if (old == NBLK - 1) {
                atomicExch(&g_count, 0u);
                __threadfence();
                atomicAdd(&g_gen, 1u);
            } else {
                const unsigned target = gen0 + (unsigned)(s + 1);
                while ((int)(*((volatile unsigned*)&g_gen) - target) < 0) { }
            }
            __threadfence();
        }
        __syncthreads();
    }
}

// =========================================================================
// K2: logits GEMM [64,1024]x[1024,50257] + relu + per-row expsum.
// Thread tile: 2 v (packed f32x2) x 8 t. SMEM-staged tiles, k-tile = 128.
// =========================================================================
#define VBLK 64
#define K2_BLOCKS ((V_SIZE + VBLK - 1) / VBLK)
#define KT 128
#define K2_W_STRIDE 66   // padded [128][66] fp32, transposed (k-major)
#define K2_H_STRIDE 65   // padded [128][65] float2 (h duplicated in both lanes)
#define K2_SMEM (KT * K2_W_STRIDE * sizeof(float) + KT * K2_H_STRIDE * sizeof(float2))

__device__ __forceinline__ unsigned long long fma2(unsigned long long a,
                                                   unsigned long long b,
                                                   unsigned long long c) {
    unsigned long long d;
    asm("fma.rn.f32x2 %0, %1, %2, %3;" : "=l"(d) : "l"(a), "l"(b), "l"(c));
    return d;
}

__global__ void __launch_bounds__(256, 2) gemm_kernel(
    const float* __restrict__ linW, const float* __restrict__ linb,
    float* __restrict__ out)
{
    extern __shared__ float sm[];
    float*  w_s  = sm;                                   // [KT][66]
    float2* hs_d = (float2*)(sm + KT * K2_W_STRIDE);     // [KT][65]

    const int tid = threadIdx.x;
    const int vp  = tid & 31;        // v-pair index within block (v = 2*vp, 2*vp+1)
    const int tq  = tid >> 5;        // warp id -> t group
    const int t0  = tq * 8;
    const int v0  = blockIdx.x * VBLK;

    unsigned long long acc[8];
    #pragma unroll
    for (int j = 0; j < 8; j++) acc[j] = 0ull;

    for (int kt = 0; kt < HID / KT; kt++) {
        const int k0 = kt * KT;
        __syncthreads();
        // W tile, transposed to k-major
        for (int i = tid; i < VBLK * KT; i += 256) {
            const int row = i >> 7;
            const int col = i & 127;
            const int v = v0 + row;
            float val = (v < V_SIZE) ? linW[(size_t)v * HID + k0 + col] : 0.0f;
            w_s[col * K2_W_STRIDE + row] = val;
        }
        // hs tile, duplicated into both f32x2 lanes
        for (int i = tid; i < TLEN * KT; i += 256) {
            const int t = i >> 7;
            const int k = i & 127;
            float h = g_hs[t * HID + k0 + k];
            hs_d[k * K2_H_STRIDE + t] = make_float2(h, h);
        }
        __syncthreads();

        #pragma unroll 4
        for (int k = 0; k < KT; k++) {
            unsigned long long w2 =
                *((const unsigned long long*)(w_s + k * K2_W_STRIDE + 2 * vp));
            const float2* hrow = hs_d + k * K2_H_STRIDE + t0;
            #pragma unroll
            for (int j = 0; j < 8; j++) {
                unsigned long long h2 = *((const unsigned long long*)(hrow + j));
                acc[j] = fma2(h2, w2, acc[j]);
            }
        }
    }

    const int va = v0 + 2 * vp;
    const int vb = va + 1;
    const float lba = (va < V_SIZE) ? linb[va] : 0.0f;
    const float lbb = (vb < V_SIZE) ? linb[vb] : 0.0f;
    #pragma unroll
    for (int j = 0; j < 8; j++) {
        float lo = __uint_as_float((unsigned)(acc[j] & 0xffffffffull));
        float hi = __uint_as_float((unsigned)(acc[j] >> 32));
        float r0 = fmaxf(lo + lba, 0.0f);
        float r1 = fmaxf(hi + lbb, 0.0f);
        float e = 0.0f;
        const int t = t0 + j;
        if (va < V_SIZE) { out[(size_t)t * V_SIZE + va] = r0; e += __expf(r0); }
        if (vb < V_SIZE) { out[(size_t)t * V_SIZE + vb] = r1; e += __expf(r1); }
        #pragma unroll
        for (int o = 16; o > 0; o >>= 1) e += __shfl_down_sync(0xffffffffu, e, o);
        if (vp == 0) atomicAdd(&g_rowsum[t], e);
    }
}

// =========================================================================
// K3: out[t][v] -= log(rowsum[t])   (unshifted LSE is safe: logits are small,
// relu >= 0 so rowsum >= V, exp args bounded well within fp32 range)
// =========================================================================
__global__ void finish_kernel(float* __restrict__ out) {
    __shared__ float ls;
    const int t = blockIdx.y;
    if (threadIdx.x == 0) ls = logf(g_rowsum[t]);
    __syncthreads();
    const int v = blockIdx.x * 256 + threadIdx.x;
    if (v < V_SIZE) out[(size_t)t * V_SIZE + v] -= ls;
}

// =========================================================================
extern "C" void kernel_launch(void* const* d_in, const int* in_sizes, int n_in,
                              void* d_out, int out_size) {
    (void)in_sizes; (void)n_in; (void)out_size;
    const int*   seq   = (const int*)d_in[0];
    const float* feats = (const float*)d_in[1];
    const int*   dseq  = (const int*)d_in[2];
    const float* emb   = (const float*)d_in[3];
    const float* eWih  = (const float*)d_in[4];
    const float* eWhh  = (const float*)d_in[5];
    const float* ebih  = (const float*)d_in[6];
    const float* ebhh  = (const float*)d_in[7];
    const float* dWih  = (const float*)d_in[8];
    const float* dWhh  = (const float*)d_in[9];
    const float* dbih  = (const float*)d_in[10];
    const float* dbhh  = (const float*)d_in[11];
    const float* linW  = (const float*)d_in[12];
    const float* linb  = (const float*)d_in[13];
    float* out = (float*)d_out;

    cudaFuncSetAttribute(lstm_kernel, cudaFuncAttributeMaxDynamicSharedMemorySize, (int)K1_SMEM);
    cudaFuncSetAttribute(gemm_kernel, cudaFuncAttributeMaxDynamicSharedMemorySize, (int)K2_SMEM);

    lstm_kernel<<<NBLK, 256, K1_SMEM>>>(seq, feats, dseq, emb,
                                        eWih, eWhh, ebih, ebhh,
                                        dWih, dWhh, dbih, dbhh);
    gemm_kernel<<<K2_BLOCKS, 256, K2_SMEM>>>(linW, linb, out);
    dim3 fg((V_SIZE + 255) / 256, TLEN);
    finish_kernel<<<fg, 256>>>(out);
}

// round 3
// speedup vs baseline: 1.2974x; 1.2974x over previous
#include <cuda_runtime.h>
#include <cuda_bf16.h>
#include <math.h>

#define V_SIZE 50257
#define EMB    512
#define HID    1024
#define AFEAT  64
#define TLEN   64
#define NBLK   128
#define UNITS  8

// ---------------- device scratch ----------------
__device__ float g_h[2][HID];
__device__ float g_hs[TLEN * HID];
__device__ float g_rowsum[TLEN];
__device__ float g_xp[128 * 4096];          // input projections [step][gate-row]
__device__ unsigned g_flag[NBLK];            // per-block step flags (monotonic)
__device__ unsigned g_step_base = 0;         // epoch, bumped once per launch by K0

__device__ __forceinline__ float sigf(float x) { return 1.0f / (1.0f + __expf(-x)); }

__device__ __forceinline__ unsigned ldcg_u32(const unsigned* p) {
    unsigned v;
    asm volatile("ld.global.cg.u32 %0, [%1];" : "=r"(v) : "l"(p) : "memory");
    return v;
}
__device__ __forceinline__ unsigned long long fma2(unsigned long long a,
                                                   unsigned long long b,
                                                   unsigned long long c) {
    unsigned long long d;
    asm("fma.rn.f32x2 %0, %1, %2, %3;" : "=l"(d) : "l"(a), "l"(b), "l"(c));
    return d;
}
__device__ __forceinline__ unsigned long long pack2(float x) {
    unsigned long long d;
    asm("mov.b64 %0, {%1, %1};" : "=l"(d) : "f"(x));
    return d;
}

// =========================================================================
// K0: input projections xp[s][row] = x_s @ Wih_row + bih + bhh.
// gridDim = (64, 2): bx = 64-row tile, by = 0 enc / 1 dec. 256 threads.
// Also bumps the barrier epoch and zeroes g_rowsum (runs before K1/K2).
// =========================================================================
__global__ void __launch_bounds__(256) xproj_kernel(
    const int*   __restrict__ seq,  const int*   __restrict__ dseq,
    const float* __restrict__ feats, const float* __restrict__ emb,
    const float* __restrict__ eWih, const float* __restrict__ ebih,
    const float* __restrict__ ebhh,
    const float* __restrict__ dWih, const float* __restrict__ dbih,
    const float* __restrict__ dbhh)
{
    __shared__ float  w_s[64 * 65];            // [kk][row]
    __shared__ float2 x2_s[64 * 33];           // [kk][step-pair]

    const int tid  = threadIdx.x;
    const int wid  = tid >> 5;
    const int lane = tid & 31;
    const int bx   = blockIdx.x;
    const int by   = blockIdx.y;   // 0 = encoder, 1 = decoder

    if (bx == 0 && by == 0) {
        if (tid == 0) g_step_base += 256;
        if (tid < TLEN) g_rowsum[tid] = 0.0f;
    }

    const int KDIM = by ? (EMB + AFEAT) : EMB;
    const int NT   = KDIM / 64;                 // 8 or 9
    const float* Wih = by ? dWih : eWih;
    const float* bi  = by ? dbih : ebih;
    const float* bh  = by ? dbhh : ebhh;
    const int* toks  = by ? dseq : seq;

    const int sp0  = (wid & 3) * 8;             // 8 step-pairs = 16 steps
    const int row  = (wid >> 2) * 32 + lane;    // 0..63
    const int grow = bx * 64 + row;

    unsigned long long acc[8];
    #pragma unroll
    for (int p = 0; p < 8; p++) acc[p] = 0ull;

    for (int kt = 0; kt < NT; kt++) {
        const int k0 = kt * 64;
        __syncthreads();
        // stage x pairs: x2_s[kk][sp] = (x[2sp][k0+kk], x[2sp+1][k0+kk])
        for (int i = tid; i < 64 * 32; i += 256) {
            const int sp = i >> 6;
            const int kk = i & 63;
            const int k  = k0 + kk;
            float a, b;
            if (k < EMB) {
                a = emb[(size_t)toks[2 * sp] * EMB + k];
                b = emb[(size_t)toks[2 * sp + 1] * EMB + k];
            } else {
                a = feats[k - EMB];
                b = a;
            }
            x2_s[kk * 33 + sp] = make_float2(a, b);
        }
        // stage weights: w_s[kk][row]
        for (int i = tid; i < 64 * 64; i += 256) {
            const int r  = i >> 6;
            const int kk = i & 63;
            w_s[kk * 65 + r] = Wih[(size_t)(bx * 64 + r) * KDIM + k0 + kk];
        }
        __syncthreads();

        #pragma unroll 4
        for (int k = 0; k < 64; k++) {
            unsigned long long wd = pack2(w_s[k * 65 + row]);
            const unsigned long long* xr =
                (const unsigned long long*)(x2_s + k * 33 + sp0);
            #pragma unroll
            for (int p = 0; p < 8; p++) acc[p] = fma2(xr[p], wd, acc[p]);
        }
    }

    const float bias = bi[grow] + bh[grow];
    const int sbase = by * 64;
    #pragma unroll
    for (int p = 0; p < 8; p++) {
        float lo = __uint_as_float((unsigned)(acc[p] & 0xffffffffull));
        float hi = __uint_as_float((unsigned)(acc[p] >> 32));
        const int s = sbase + 2 * (sp0 + p);
        g_xp[(size_t)s * 4096 + grow]       = lo + bias;
        g_xp[(size_t)(s + 1) * 4096 + grow] = hi + bias;
    }
}

// =========================================================================
// K1: persistent LSTM recurrence. 128 blocks x 512 threads.
// Whh in registers (warp = 2 gate rows, 64 w-regs/thread). Flag barrier:
// one stcg per block per step, 128-thread poll + __syncthreads_and.
// =========================================================================
__global__ void __launch_bounds__(512, 1) lstm_kernel(
    const float* __restrict__ eWhh, const float* __restrict__ dWhh)
{
    __shared__ float xp_s[128 * 32];
    __shared__ __align__(16) float h_s[HID];
    __shared__ float gates_s[32];
    __shared__ float c_s[UNITS];

    const int tid  = threadIdx.x;
    const int wid  = tid >> 5;
    const int lane = tid & 31;
    const int blk  = blockIdx.x;
    const int j0   = blk * UNITS;

    const unsigned base = ldcg_u32(&g_step_base);

    // stage this block's xp slice: xp_s[s*32 + r]
    for (int i = tid; i < 128 * 32; i += 512) {
        const int s = i >> 5;
        const int r = i & 31;
        const int grow = ((r >> 3) << 10) + j0 + (r & 7);
        xp_s[i] = g_xp[(size_t)s * 4096 + grow];
    }
    if (tid < UNITS) c_s[tid] = 0.0f;

    // register-resident Whh: warp owns rows r0 = 2*wid, r1 = r0+1
    const int r0 = 2 * wid, r1 = r0 + 1;
    const size_t grow0 = (size_t)((r0 >> 3) << 10) + j0 + (r0 & 7);
    const size_t grow1 = (size_t)((r1 >> 3) << 10) + j0 + (r1 & 7);
    float4 w0[8], w1[8];
    #pragma unroll
    for (int q = 0; q < 8; q++) {
        w0[q] = *(const float4*)(eWhh + grow0 * HID + q * 128 + lane * 4);
        w1[q] = *(const float4*)(eWhh + grow1 * HID + q * 128 + lane * 4);
    }
    __syncthreads();

    for (int s = 0; s < 128; s++) {
        if (s == 64) {   // swap to decoder weights
            #pragma unroll
            for (int q = 0; q < 8; q++) {
                w0[q] = *(const float4*)(dWhh + grow0 * HID + q * 128 + lane * 4);
                w1[q] = *(const float4*)(dWhh + grow1 * HID + q * 128 + lane * 4);
            }
        }
        if (s > 0) {
            // ---- flag barrier: wait until all blocks finished step s-1 ----
            const unsigned target = base + (unsigned)s;
            bool ok = (tid < NBLK) ? ((int)(ldcg_u32(&g_flag[tid]) - target) >= 0)
                                   : true;
            while (!__syncthreads_and(ok)) {
                __nanosleep(64);   // back off only when genuinely waiting
                ok = (tid < NBLK) ? ((int)(ldcg_u32(&g_flag[tid]) - target) >= 0)
                                  : true;
            }

            // stage h (4KB) into SMEM once, then register GEMV
            const float2* hb = (const float2*)g_h[s & 1];
            ((float2*)h_s)[tid] = __ldcg(&hb[tid]);
            __syncthreads();

            float a0 = 0.0f, a1 = 0.0f;
            #pragma unroll
            for (int q = 0; q < 8; q++) {
                const float4 h4 = *(const float4*)(h_s + q * 128 + lane * 4);
                a0 = fmaf(w0[q].x, h4.x, a0); a0 = fmaf(w0[q].y, h4.y, a0);
                a0 = fmaf(w0[q].z, h4.z, a0); a0 = fmaf(w0[q].w, h4.w, a0);
                a1 = fmaf(w1[q].x, h4.x, a1); a1 = fmaf(w1[q].y, h4.y, a1);
                a1 = fmaf(w1[q].z, h4.z, a1); a1 = fmaf(w1[q].w, h4.w, a1);
            }
            #pragma unroll
            for (int o = 16; o > 0; o >>= 1) {
                a0 += __shfl_down_sync(0xffffffffu, a0, o);
                a1 += __shfl_down_sync(0xffffffffu, a1, o);
            }
            if (lane == 0) { gates_s[r0] = a0; gates_s[r1] = a1; }
        } else {
            if (tid < 32) gates_s[tid] = 0.0f;
        }
        __syncthreads();

        if (tid < UNITS) {
            const int u = tid;
            const float* xp = xp_s + s * 32;
            const float gi = gates_s[u]      + xp[u];
            const float gf = gates_s[8 + u]  + xp[8 + u];
            const float gg = gates_s[16 + u] + xp[16 + u];
            const float go = gates_s[24 + u] + xp[24 + u];
            const float c  = sigf(gf) * c_s[u] + sigf(gi) * tanhf(gg);
            c_s[u] = c;
            const float h = sigf(go) * tanhf(c);
            const int j = j0 + u;
            __stcg(&g_h[(s + 1) & 1][j], h);
            if (s >= 64) __stcg(&g_hs[(s - 64) * HID + j], h);
            __threadfence();
        }
        __syncthreads();
        if (tid == 0 && s < 127)
            __stcg(&g_flag[blk], base + (unsigned)(s + 1));
    }
}

// =========================================================================
// K2: logits GEMM [64,1024]x[1024,50257] + relu + expsum.
// VBLK=256 v x all 64 t per block; thread tile = 4v x 16t (t-paired f32x2).
// w scalar loads conflict-free (v strided by 32 per lane); h2 warp-broadcast.
// =========================================================================
#define K2_VBLK 256
#define K2_KT   64
#define K2_WS   257
#define K2_SMEM (K2_KT * K2_WS * sizeof(float) + K2_KT * 33 * sizeof(float2))

__global__ void __launch_bounds__(256, 2) gemm_kernel(
    const float* __restrict__ linW, const float* __restrict__ linb,
    float* __restrict__ out)
{
    extern __shared__ float sm[];
    float*  w_s  = sm;                              // [64][257]  (k-major)
    float2* h2_s = (float2*)(sm + K2_KT * K2_WS);   // [64][33]   (t-pairs)

    const int tid   = threadIdx.x;
    const int wid   = tid >> 5;
    const int lane  = tid & 31;
    const int tp0   = (wid & 3) * 8;       // 8 t-pairs = 16 t
    const int vhalf = (wid >> 2) * 128;
    const int v0    = blockIdx.x * K2_VBLK;

    unsigned long long acc[4][8];
    #pragma unroll
    for (int j = 0; j < 4; j++)
        #pragma unroll
        for (int p = 0; p < 8; p++) acc[j][p] = 0ull;

    for (int kt = 0; kt < HID / K2_KT; kt++) {
        const int k0 = kt * K2_KT;
        __syncthreads();
        // stage W (transposed): thread loads float4 along k, scatters 4 scalars
        for (int i = tid; i < 16 * 256; i += 256) {
            const int kk4 = i & 15;
            const int vv  = i >> 4;
            const int v   = v0 + vv;
            float4 w4 = make_float4(0.f, 0.f, 0.f, 0.f);
            if (v < V_SIZE)
                w4 = *(const float4*)(linW + (size_t)v * HID + k0 + kk4 * 4);
            w_s[(4 * kk4 + 0) * K2_WS + vv] = w4.x;
            w_s[(4 * kk4 + 1) * K2_WS + vv] = w4.y;
            w_s[(4 * kk4 + 2) * K2_WS + vv] = w4.z;
            w_s[(4 * kk4 + 3) * K2_WS + vv] = w4.w;
        }
        // stage h pairs: h2_s[kk][tp] = (hs[2tp][k], hs[2tp+1][k])
        for (int i = tid; i < 64 * 32; i += 256) {
            const int tp = i >> 6;
            const int kk = i & 63;
            h2_s[kk * 33 + tp] = make_float2(g_hs[(2 * tp) * HID + k0 + kk],
                                             g_hs[(2 * tp + 1) * HID + k0 + kk]);
        }
        __syncthreads();

        #pragma unroll 4
        for (int k = 0; k < K2_KT; k++) {
            const float* wr = w_s + k * K2_WS + vhalf + lane;
            unsigned long long wd[4];
            #pragma unroll
            for (int j = 0; j < 4; j++) wd[j] = pack2(wr[32 * j]);
            const unsigned long long* hr =
                (const unsigned long long*)(h2_s + k * 33 + tp0);
            #pragma unroll
            for (int p = 0; p < 8; p++) {
                const unsigned long long h2 = hr[p];
                #pragma unroll
                for (int j = 0; j < 4; j++)
                    acc[j][p] = fma2(h2, wd[j], acc[j][p]);
            }
        }
    }

    // epilogue: bias + relu + store + expsum
    float lb[4];
    int vv[4];
    #pragma unroll
    for (int j = 0; j < 4; j++) {
        vv[j] = v0 + vhalf + lane + 32 * j;
        lb[j] = (vv[j] < V_SIZE) ? linb[vv[j]] : 0.0f;
    }
    float es[16];
    #pragma unroll
    for (int i = 0; i < 16; i++) es[i] = 0.0f;

    #pragma unroll
    for (int p = 0; p < 8; p++) {
        const int ta = (tp0 + p) * 2;
        #pragma unroll
        for (int j = 0; j < 4; j++) {
            if (vv[j] >= V_SIZE) continue;
            const float lo = __uint_as_float((unsigned)(acc[j][p] & 0xffffffffull));
            const float hi = __uint_as_float((unsigned)(acc[j][p] >> 32));
            const float ra = fmaxf(lo + lb[j], 0.0f);
            const float rb = fmaxf(hi + lb[j], 0.0f);
            out[(size_t)ta * V_SIZE + vv[j]]       = ra;
            out[(size_t)(ta + 1) * V_SIZE + vv[j]] = rb;
            es[2 * p]     += __expf(ra);
            es[2 * p + 1] += __expf(rb);
        }
    }
    const int tbase = (wid & 3) * 16;
    #pragma unroll
    for (int i = 0; i < 16; i++) {
        float e = es[i];
        #pragma unroll
        for (int o = 16; o > 0; o >>= 1) e += __shfl_down_sync(0xffffffffu, e, o);
        if (lane == 0) atomicAdd(&g_rowsum[tbase + i], e);
    }
}

// =========================================================================
// K3: out[t][v] -= log(rowsum[t])
// =========================================================================
__global__ void finish_kernel(float* __restrict__ out) {
    __shared__ float ls;
    const int t = blockIdx.y;
    if (threadIdx.x == 0) ls = logf(g_rowsum[t]);
    __syncthreads();
    const int v = blockIdx.x * 256 + threadIdx.x;
    if (v < V_SIZE) out[(size_t)t * V_SIZE + v] -= ls;
}

// =========================================================================
extern "C" void kernel_launch(void* const* d_in, const int* in_sizes, int n_in,
                              void* d_out, int out_size) {
    (void)in_sizes; (void)n_in; (void)out_size;
    const int*   seq   = (const int*)d_in[0];
    const float* feats = (const float*)d_in[1];
    const int*   dseq  = (const int*)d_in[2];
    const float* emb   = (const float*)d_in[3];
    const float* eWih  = (const float*)d_in[4];
    const float* eWhh  = (const float*)d_in[5];
    const float* ebih  = (const float*)d_in[6];
    const float* ebhh  = (const float*)d_in[7];
    const float* dWih  = (const float*)d_in[8];
    const float* dWhh  = (const float*)d_in[9];
    const float* dbih  = (const float*)d_in[10];
    const float* dbhh  = (const float*)d_in[11];
    const float* linW  = (const float*)d_in[12];
    const float* linb  = (const float*)d_in[13];
    float* out = (float*)d_out;

    cudaFuncSetAttribute(gemm_kernel, cudaFuncAttributeMaxDynamicSharedMemorySize,
                         (int)K2_SMEM);

    dim3 g0(64, 2);
    xproj_kernel<<<g0, 256>>>(seq, dseq, feats, emb,
                              eWih, ebih, ebhh, dWih, dbih, dbhh);
    lstm_kernel<<<NBLK, 512>>>(eWhh, dWhh);
    const int k2_blocks = (V_SIZE + K2_VBLK - 1) / K2_VBLK;
    gemm_kernel<<<k2_blocks, 256, K2_SMEM>>>(linW, linb, out);
    dim3 fg((V_SIZE + 255) / 256, TLEN);
    finish_kernel<<<fg, 256>>>(out);
}